// round 9
// baseline (speedup 1.0000x reference)
#include <cuda_runtime.h>

// GMM score, d=1, fused persistent kernel, hybrid MUFU/FMA exponential.
//   sigma2(t) = (exp(2 t ln25) - 1) / (2 ln25)
//   e_ij = 2^( (k*tr + c1)*tr + c0 ),  k = -1/(2 ln2 sigma2)
//   out[j] = (num/den - x[j]) / sigma2[j]   (den==0 guard as reference)
//
// Phase A: units (query-warp x train-chunk), C chosen so units divide warp
// count exactly. 13 of 16 pairs via MUFU ex2; 3 of 16 via lean packed
// FMA-pipe exp2 (magic round, IMAD scale, deg-4 f32x2 Horner, FMNMX clamp).
// Model (rt2 f32x2, confirmed by R6 fma-busy%): MUFU 13 cyc/pair binds,
// FMA 11.75, issue 10.3. 6 warps/SMSP to hide the Horner chain latency.
// Grid barrier (monotonic epoch, grid == SM count, 1 CTA/SM).
// Phase B in-kernel: thread-per-query reduction of C partials + epilogue.

#define TPB       768
#define WPB       (TPB / 32)
#define MAXB      16384
#define CMAX      128

typedef unsigned long long u64;

__device__ float2 g_part[CMAX * MAXB];
__device__ unsigned int g_arrive = 0;

#define PACK2(d, lo, hi) \
    asm("mov.b64 %0, {%1, %2};" : "=l"(d) : "f"(lo), "f"(hi))
#define UNPACK2(lo, hi, s) \
    asm("mov.b64 {%0, %1}, %2;" : "=f"(lo), "=f"(hi) : "l"(s))
#define FMA2(d, a, b, c) \
    asm("fma.rn.f32x2 %0, %1, %2, %3;" : "=l"(d) : "l"(a), "l"(b), "l"(c))
#define ADD2(d, a, b) \
    asm("add.rn.f32x2 %0, %1, %2;" : "=l"(d) : "l"(a), "l"(b))
#define MUL2(d, a, b) \
    asm("mul.rn.f32x2 %0, %1, %2;" : "=l"(d) : "l"(a), "l"(b))
#define EX2(d, a) \
    asm("ex2.approx.ftz.f32 %0, %1;" : "=f"(d) : "f"(a))

struct PolyC {
    u64 MG2, MG2N, NEG1, PC4, PC3, PC2, PC1, PC0;
};

__device__ __forceinline__ float sigma2_of(float tv) {
    const float LOG_S = 3.2188758248682006f;   // ln 25
    return (expf(2.0f * tv * LOG_S) - 1.0f) / (2.0f * LOG_S);
}

// MUFU path: 4 packed FMA ops + 2 MUFU ex2 per pair
__device__ __forceinline__ void pair_mufu(u64 P, u64 KK, u64 C1c, u64 C0c,
                                          u64& num2, u64& den2)
{
    u64 t1, a2, E;
    FMA2(t1, KK, P, C1c);
    FMA2(a2, t1, P, C0c);
    float al, ah, e0, e1;
    UNPACK2(al, ah, a2);
    EX2(e0, al);
    EX2(e1, ah);
    PACK2(E, e0, e1);
    FMA2(num2, E, P, num2);
    ADD2(den2, den2, E);
}

// FMA-pipe path: 12 packed fma-pipe ops + 2 IMAD (+2 FMNMX on ALU) per pair
__device__ __forceinline__ void pair_poly(u64 P, u64 KK, u64 C1c, u64 C0c,
                                          const PolyC& pc,
                                          u64& num2, u64& den2)
{
    u64 t1, a2;
    FMA2(t1, KK, P, C1c);
    FMA2(a2, t1, P, C0c);
    float a0, a1;
    UNPACK2(a0, a1, a2);
    a0 = fmaxf(a0, -126.0f);                  // FMNMX (alu pipe)
    a1 = fmaxf(a1, -126.0f);
    u64 ac; PACK2(ac, a0, a1);
    u64 r2; ADD2(r2, ac, pc.MG2);             // r = a + MAGIC (round to int)
    u64 n2; ADD2(n2, r2, pc.MG2N);            // n = r - MAGIC (exact)
    u64 f2; FMA2(f2, n2, pc.NEG1, ac);        // f = a - n, f in [-0.5, 0.5]
    float r0, r1;
    UNPACK2(r0, r1, r2);
    unsigned s0 = __float_as_uint(r0) * 0x800000u + 0x3F800000u;  // 2^n bits
    unsigned s1 = __float_as_uint(r1) * 0x800000u + 0x3F800000u;
    u64 pp;
    FMA2(pp, pc.PC4, f2, pc.PC3);             // deg-4 Horner for 2^f
    FMA2(pp, pp, f2, pc.PC2);
    FMA2(pp, pp, f2, pc.PC1);
    FMA2(pp, pp, f2, pc.PC0);
    u64 S; PACK2(S, __uint_as_float(s0), __uint_as_float(s1));
    u64 E; MUL2(E, pp, S);
    FMA2(num2, E, P, num2);
    ADD2(den2, den2, E);
}

__global__ __launch_bounds__(TPB, 1)
void gmm_fused_kernel(const float* __restrict__ x,
                      const float* __restrict__ t,
                      const float* __restrict__ train,
                      float* __restrict__ out,
                      int B, int N, int C, int PL /* pairs/chunk, even */)
{
    extern __shared__ u64 sp[];    // C*PL packed train pairs

    // Stage train pre-packed; pad -6e17: finite exponent chain, e==0 (mufu)
    // or ~1.2e-38 (poly, clamped) -> negligible.
    const int tot = C * PL;
    for (int i = threadIdx.x; i < tot; i += TPB) {
        int e0 = 2 * i, e1 = 2 * i + 1;
        float a = (e0 < N) ? train[e0] : -6e17f;
        float b = (e1 < N) ? train[e1] : -6e17f;
        u64 pk;
        PACK2(pk, a, b);
        sp[i] = pk;
    }
    __syncthreads();

    const int lane   = threadIdx.x & 31;
    const int wid    = threadIdx.x >> 5;
    const int wgid   = blockIdx.x * WPB + wid;
    const int nwarps = gridDim.x * WPB;

    const int qwarps = (B + 31) >> 5;
    const int units  = qwarps * C;

    const float INV_LN2 = 1.4426950408889634f;
    const float MAGIC   = 12582912.0f;         // 1.5 * 2^23

    PolyC pc;
    PACK2(pc.MG2,  MAGIC,  MAGIC);
    PACK2(pc.MG2N, -MAGIC, -MAGIC);
    PACK2(pc.NEG1, -1.0f, -1.0f);
    {
        const float c4 = 0.0096181291f, c3 = 0.0555041087f,
                    c2 = 0.2402265070f, c1p = 0.6931471806f, c0p = 1.0f;
        PACK2(pc.PC4, c4, c4); PACK2(pc.PC3, c3, c3); PACK2(pc.PC2, c2, c2);
        PACK2(pc.PC1, c1p, c1p); PACK2(pc.PC0, c0p, c0p);
    }

    // ---- phase A ----
    for (int u = wgid; u < units; u += nwarps) {
        const int qw = u / C;
        const int c  = u - qw * C;
        const int q  = qw * 32 + lane;
        const bool act = (q < B);

        float xv = 0.0f, tv = 0.5f;
        if (act) { xv = x[q]; tv = t[q]; }

        const float sigma2 = sigma2_of(tv);
        const float k  = -0.5f * INV_LN2 / sigma2;
        const float c1 = -2.0f * k * xv;
        const float c0 = k * xv * xv;

        u64 KK, C1c, C0c, num2 = 0ULL, den2 = 0ULL;
        PACK2(KK, k, k);
        PACK2(C1c, c1, c1);
        PACK2(C0c, c0, c0);

        const ulonglong2* __restrict__ p =
            reinterpret_cast<const ulonglong2*>(sp + c * PL);
        const int iters  = PL >> 1;            // vec4 loads (2 pairs each)
        const int blocks = iters >> 3;         // 16 pairs per block

        int i = 0;
        for (int b = 0; b < blocks; ++b, i += 8) {
            // 16 pairs: poly on pairs 2, 7, 12 (3/16), mufu elsewhere
            ulonglong2 v0 = p[i + 0];
            ulonglong2 v1 = p[i + 1];
            ulonglong2 v2 = p[i + 2];
            ulonglong2 v3 = p[i + 3];
            pair_mufu(v0.x, KK, C1c, C0c, num2, den2);        // 0
            pair_mufu(v0.y, KK, C1c, C0c, num2, den2);        // 1
            pair_poly(v1.x, KK, C1c, C0c, pc, num2, den2);    // 2
            pair_mufu(v1.y, KK, C1c, C0c, num2, den2);        // 3
            pair_mufu(v2.x, KK, C1c, C0c, num2, den2);        // 4
            pair_mufu(v2.y, KK, C1c, C0c, num2, den2);        // 5
            pair_mufu(v3.x, KK, C1c, C0c, num2, den2);        // 6
            pair_poly(v3.y, KK, C1c, C0c, pc, num2, den2);    // 7
            ulonglong2 v4 = p[i + 4];
            ulonglong2 v5 = p[i + 5];
            ulonglong2 v6 = p[i + 6];
            ulonglong2 v7 = p[i + 7];
            pair_mufu(v4.x, KK, C1c, C0c, num2, den2);        // 8
            pair_mufu(v4.y, KK, C1c, C0c, num2, den2);        // 9
            pair_mufu(v5.x, KK, C1c, C0c, num2, den2);        // 10
            pair_mufu(v5.y, KK, C1c, C0c, num2, den2);        // 11
            pair_poly(v6.x, KK, C1c, C0c, pc, num2, den2);    // 12
            pair_mufu(v6.y, KK, C1c, C0c, num2, den2);        // 13
            pair_mufu(v7.x, KK, C1c, C0c, num2, den2);        // 14
            pair_mufu(v7.y, KK, C1c, C0c, num2, den2);        // 15
        }
        for (; i < iters; ++i) {               // tail pairs (mufu)
            ulonglong2 v = p[i];
            pair_mufu(v.x, KK, C1c, C0c, num2, den2);
            pair_mufu(v.y, KK, C1c, C0c, num2, den2);
        }

        float nlo, nhi, dlo, dhi;
        UNPACK2(nlo, nhi, num2);
        UNPACK2(dlo, dhi, den2);
        if (act)
            g_part[c * MAXB + q] = make_float2(nlo + nhi, dlo + dhi);
    }

    // ---- grid barrier (monotonic epoch; grid == SM count, all resident) ----
    __syncthreads();
    if (threadIdx.x == 0) {
        __threadfence();
        unsigned old = atomicAdd(&g_arrive, 1u);
        unsigned target = (old / gridDim.x + 1u) * gridDim.x;
        while (*((volatile unsigned int*)&g_arrive) < target) { }
    }
    __syncthreads();
    __threadfence();

    // ---- phase B ----
    const int gq = blockIdx.x * TPB + threadIdx.x;
    if (gq < B) {
        float num = 0.0f, den = 0.0f;
        for (int c = 0; c < C; ++c) {
            float2 pd = g_part[c * MAXB + gq];
            num += pd.x;
            den += pd.y;
        }
        float xv = x[gq];
        float sigma2 = sigma2_of(t[gq]);
        float evals = (den == 0.0f) ? 0.0f : (num / den);
        out[gq] = (evals - xv) / sigma2;
    }
}

static int gcd_i(int a, int b) { while (b) { int r = a % b; a = b; b = r; } return a; }

extern "C" void kernel_launch(void* const* d_in, const int* in_sizes, int n_in,
                              void* d_out, int out_size)
{
    const float* x     = (const float*)d_in[0];
    const float* t     = (const float*)d_in[1];
    const float* train = (const float*)d_in[2];
    float* out = (float*)d_out;

    int B = in_sizes[0];   // 16384
    int N = in_sizes[2];   // 16384

    static int sms = 0;
    static int C = 0, PL = 0;
    static size_t smem = 0;
    if (!sms) {
        cudaDeviceGetAttribute(&sms, cudaDevAttrMultiProcessorCount, 0);
        if (sms <= 0) sms = 148;

        int warps  = sms * WPB;
        int qwarps = (B + 31) / 32;
        C = warps / gcd_i(qwarps, warps);          // exact static balance
        if (C > CMAX) C = CMAX;                    // fallback (imperfect balance)
        if (C < 8)  C *= (8 + C - 1) / C;          // keep enough chunks
        int npairs = (N + 1) / 2;
        PL = (npairs + C - 1) / C;
        PL = (PL + 1) & ~1;                        // even (LDS.128)
        smem = (size_t)C * PL * sizeof(u64);
        cudaFuncSetAttribute(gmm_fused_kernel,
                             cudaFuncAttributeMaxDynamicSharedMemorySize,
                             (int)smem);
    }

    gmm_fused_kernel<<<sms, TPB, smem>>>(x, t, train, out, B, N, C, PL);
}

// round 10
// speedup vs baseline: 1.1026x; 1.1026x over previous
#include <cuda_runtime.h>

// GMM score, d=1, fused persistent kernel, hybrid MUFU/FMA exponential.
//   sigma2(t) = (exp(2 t ln25) - 1) / (2 ln25)
//   e_ij = 2^( (k*tr + c1)*tr + c0 ),  k = -1/(2 ln2 sigma2)
//   out[j] = (num/den - x[j]) / sigma2[j]   (den==0 guard as reference)
//
// R9 = R6 config (TPB=512 -> C=19, 4 units/warp) with two isolated changes:
//  * phi = 3/16 poly pairs (MUFU bind 13 cyc/pair, FMA 11.75, issue 10.3)
//  * phase B: 4 threads/query, shuffle-combined (5-load chain instead of 19)
// Grid barrier (monotonic epoch, grid == SM count, 1 CTA/SM resident).

#define TPB       512
#define WPB       (TPB / 32)
#define MAXB      16384
#define CMAX      128

typedef unsigned long long u64;

__device__ float2 g_part[CMAX * MAXB];
__device__ unsigned int g_arrive = 0;

#define PACK2(d, lo, hi) \
    asm("mov.b64 %0, {%1, %2};" : "=l"(d) : "f"(lo), "f"(hi))
#define UNPACK2(lo, hi, s) \
    asm("mov.b64 {%0, %1}, %2;" : "=f"(lo), "=f"(hi) : "l"(s))
#define FMA2(d, a, b, c) \
    asm("fma.rn.f32x2 %0, %1, %2, %3;" : "=l"(d) : "l"(a), "l"(b), "l"(c))
#define ADD2(d, a, b) \
    asm("add.rn.f32x2 %0, %1, %2;" : "=l"(d) : "l"(a), "l"(b))
#define MUL2(d, a, b) \
    asm("mul.rn.f32x2 %0, %1, %2;" : "=l"(d) : "l"(a), "l"(b))
#define EX2(d, a) \
    asm("ex2.approx.ftz.f32 %0, %1;" : "=f"(d) : "f"(a))

struct PolyC {
    u64 MG2, MG2N, NEG1, PC4, PC3, PC2, PC1, PC0;
};

__device__ __forceinline__ float sigma2_of(float tv) {
    const float LOG_S = 3.2188758248682006f;   // ln 25
    return (expf(2.0f * tv * LOG_S) - 1.0f) / (2.0f * LOG_S);
}

// MUFU path: 4 packed FMA ops + 2 MUFU ex2 per pair
__device__ __forceinline__ void pair_mufu(u64 P, u64 KK, u64 C1c, u64 C0c,
                                          u64& num2, u64& den2)
{
    u64 t1, a2, E;
    FMA2(t1, KK, P, C1c);
    FMA2(a2, t1, P, C0c);
    float al, ah, e0, e1;
    UNPACK2(al, ah, a2);
    EX2(e0, al);
    EX2(e1, ah);
    PACK2(E, e0, e1);
    FMA2(num2, E, P, num2);
    ADD2(den2, den2, E);
}

// FMA-pipe path: 12 packed fma-pipe ops + 2 IMAD (+2 FMNMX on ALU) per pair
__device__ __forceinline__ void pair_poly(u64 P, u64 KK, u64 C1c, u64 C0c,
                                          const PolyC& pc,
                                          u64& num2, u64& den2)
{
    u64 t1, a2;
    FMA2(t1, KK, P, C1c);
    FMA2(a2, t1, P, C0c);
    float a0, a1;
    UNPACK2(a0, a1, a2);
    a0 = fmaxf(a0, -126.0f);                  // FMNMX (alu pipe)
    a1 = fmaxf(a1, -126.0f);
    u64 ac; PACK2(ac, a0, a1);
    u64 r2; ADD2(r2, ac, pc.MG2);             // r = a + MAGIC (round to int)
    u64 n2; ADD2(n2, r2, pc.MG2N);            // n = r - MAGIC (exact)
    u64 f2; FMA2(f2, n2, pc.NEG1, ac);        // f = a - n, f in [-0.5, 0.5]
    float r0, r1;
    UNPACK2(r0, r1, r2);
    unsigned s0 = __float_as_uint(r0) * 0x800000u + 0x3F800000u;  // 2^n bits
    unsigned s1 = __float_as_uint(r1) * 0x800000u + 0x3F800000u;
    u64 pp;
    FMA2(pp, pc.PC4, f2, pc.PC3);             // deg-4 Horner for 2^f
    FMA2(pp, pp, f2, pc.PC2);
    FMA2(pp, pp, f2, pc.PC1);
    FMA2(pp, pp, f2, pc.PC0);
    u64 S; PACK2(S, __uint_as_float(s0), __uint_as_float(s1));
    u64 E; MUL2(E, pp, S);
    FMA2(num2, E, P, num2);
    ADD2(den2, den2, E);
}

__global__ __launch_bounds__(TPB, 1)
void gmm_fused_kernel(const float* __restrict__ x,
                      const float* __restrict__ t,
                      const float* __restrict__ train,
                      float* __restrict__ out,
                      int B, int N, int C, int PL /* pairs/chunk, even */)
{
    extern __shared__ u64 sp[];    // C*PL packed train pairs

    // Stage train pre-packed; pad -6e17: finite exponent chain, e==0 (mufu)
    // or ~1.2e-38 (poly, clamped) -> negligible.
    const int tot = C * PL;
    for (int i = threadIdx.x; i < tot; i += TPB) {
        int e0 = 2 * i, e1 = 2 * i + 1;
        float a = (e0 < N) ? train[e0] : -6e17f;
        float b = (e1 < N) ? train[e1] : -6e17f;
        u64 pk;
        PACK2(pk, a, b);
        sp[i] = pk;
    }
    __syncthreads();

    const int lane   = threadIdx.x & 31;
    const int wid    = threadIdx.x >> 5;
    const int wgid   = blockIdx.x * WPB + wid;
    const int nwarps = gridDim.x * WPB;

    const int qwarps = (B + 31) >> 5;
    const int units  = qwarps * C;

    const float INV_LN2 = 1.4426950408889634f;
    const float MAGIC   = 12582912.0f;         // 1.5 * 2^23

    PolyC pc;
    PACK2(pc.MG2,  MAGIC,  MAGIC);
    PACK2(pc.MG2N, -MAGIC, -MAGIC);
    PACK2(pc.NEG1, -1.0f, -1.0f);
    {
        const float c4 = 0.0096181291f, c3 = 0.0555041087f,
                    c2 = 0.2402265070f, c1p = 0.6931471806f, c0p = 1.0f;
        PACK2(pc.PC4, c4, c4); PACK2(pc.PC3, c3, c3); PACK2(pc.PC2, c2, c2);
        PACK2(pc.PC1, c1p, c1p); PACK2(pc.PC0, c0p, c0p);
    }

    // ---- phase A ----
    for (int u = wgid; u < units; u += nwarps) {
        const int qw = u / C;
        const int c  = u - qw * C;
        const int q  = qw * 32 + lane;
        const bool act = (q < B);

        float xv = 0.0f, tv = 0.5f;
        if (act) { xv = x[q]; tv = t[q]; }

        const float sigma2 = sigma2_of(tv);
        const float k  = -0.5f * INV_LN2 / sigma2;
        const float c1 = -2.0f * k * xv;
        const float c0 = k * xv * xv;

        u64 KK, C1c, C0c, num2 = 0ULL, den2 = 0ULL;
        PACK2(KK, k, k);
        PACK2(C1c, c1, c1);
        PACK2(C0c, c0, c0);

        const ulonglong2* __restrict__ p =
            reinterpret_cast<const ulonglong2*>(sp + c * PL);
        const int iters  = PL >> 1;            // vec4 loads (2 pairs each)
        const int blocks = iters >> 3;         // 16 pairs per block

        int i = 0;
        for (int b = 0; b < blocks; ++b, i += 8) {
            // 16 pairs: poly on pairs 2, 7, 12 (3/16), mufu elsewhere
            ulonglong2 v0 = p[i + 0];
            ulonglong2 v1 = p[i + 1];
            ulonglong2 v2 = p[i + 2];
            ulonglong2 v3 = p[i + 3];
            pair_mufu(v0.x, KK, C1c, C0c, num2, den2);        // 0
            pair_mufu(v0.y, KK, C1c, C0c, num2, den2);        // 1
            pair_poly(v1.x, KK, C1c, C0c, pc, num2, den2);    // 2
            pair_mufu(v1.y, KK, C1c, C0c, num2, den2);        // 3
            pair_mufu(v2.x, KK, C1c, C0c, num2, den2);        // 4
            pair_mufu(v2.y, KK, C1c, C0c, num2, den2);        // 5
            pair_mufu(v3.x, KK, C1c, C0c, num2, den2);        // 6
            pair_poly(v3.y, KK, C1c, C0c, pc, num2, den2);    // 7
            ulonglong2 v4 = p[i + 4];
            ulonglong2 v5 = p[i + 5];
            ulonglong2 v6 = p[i + 6];
            ulonglong2 v7 = p[i + 7];
            pair_mufu(v4.x, KK, C1c, C0c, num2, den2);        // 8
            pair_mufu(v4.y, KK, C1c, C0c, num2, den2);        // 9
            pair_mufu(v5.x, KK, C1c, C0c, num2, den2);        // 10
            pair_mufu(v5.y, KK, C1c, C0c, num2, den2);        // 11
            pair_poly(v6.x, KK, C1c, C0c, pc, num2, den2);    // 12
            pair_mufu(v6.y, KK, C1c, C0c, num2, den2);        // 13
            pair_mufu(v7.x, KK, C1c, C0c, num2, den2);        // 14
            pair_mufu(v7.y, KK, C1c, C0c, num2, den2);        // 15
        }
        for (; i < iters; ++i) {               // tail pairs (mufu)
            ulonglong2 v = p[i];
            pair_mufu(v.x, KK, C1c, C0c, num2, den2);
            pair_mufu(v.y, KK, C1c, C0c, num2, den2);
        }

        float nlo, nhi, dlo, dhi;
        UNPACK2(nlo, nhi, num2);
        UNPACK2(dlo, dhi, den2);
        if (act)
            g_part[c * MAXB + q] = make_float2(nlo + nhi, dlo + dhi);
    }

    // ---- grid barrier (monotonic epoch; grid == SM count, all resident) ----
    __syncthreads();
    if (threadIdx.x == 0) {
        __threadfence();
        unsigned old = atomicAdd(&g_arrive, 1u);
        unsigned target = (old / gridDim.x + 1u) * gridDim.x;
        while (*((volatile unsigned int*)&g_arrive) < target) { }
    }
    __syncthreads();
    __threadfence();

    // ---- phase B: S threads per query, shuffle combine ----
    const int T  = gridDim.x * TPB;
    const int tg = blockIdx.x * TPB + threadIdx.x;
    int ls;                                       // log2(S)
    if      (T >= 4 * B) ls = 2;
    else if (T >= 2 * B) ls = 1;
    else                 ls = 0;
    const int S   = 1 << ls;
    const int gq  = tg >> ls;
    const int sub = tg & (S - 1);

    if (gq < B) {
        float num = 0.0f, den = 0.0f;
        for (int c = sub; c < C; c += S) {
            float2 pd = g_part[c * MAXB + gq];
            num += pd.x;
            den += pd.y;
        }
        // combine within the S-thread group (same warp; S divides 32)
        for (int off = S >> 1; off > 0; off >>= 1) {
            num += __shfl_down_sync(0xffffffffu, num, off);
            den += __shfl_down_sync(0xffffffffu, den, off);
        }
        if (sub == 0) {
            float xv = x[gq];
            float sigma2 = sigma2_of(t[gq]);
            float evals = (den == 0.0f) ? 0.0f : (num / den);
            out[gq] = (evals - xv) / sigma2;
        }
    }
}

static int gcd_i(int a, int b) { while (b) { int r = a % b; a = b; b = r; } return a; }

extern "C" void kernel_launch(void* const* d_in, const int* in_sizes, int n_in,
                              void* d_out, int out_size)
{
    const float* x     = (const float*)d_in[0];
    const float* t     = (const float*)d_in[1];
    const float* train = (const float*)d_in[2];
    float* out = (float*)d_out;

    int B = in_sizes[0];   // 16384
    int N = in_sizes[2];   // 16384

    static int sms = 0;
    static int C = 0, PL = 0;
    static size_t smem = 0;
    if (!sms) {
        cudaDeviceGetAttribute(&sms, cudaDevAttrMultiProcessorCount, 0);
        if (sms <= 0) sms = 148;

        int warps  = sms * WPB;
        int qwarps = (B + 31) / 32;
        C = warps / gcd_i(qwarps, warps);          // exact static balance (C=19 @152 SMs)
        if (C > CMAX) C = CMAX;                    // fallback (imperfect balance)
        if (C < 4)  C *= (4 + C - 1) / C;          // keep a few chunks for phase B
        int npairs = (N + 1) / 2;
        PL = (npairs + C - 1) / C;
        PL = (PL + 1) & ~1;                        // even (vec4 LDS)
        smem = (size_t)C * PL * sizeof(u64);
        cudaFuncSetAttribute(gmm_fused_kernel,
                             cudaFuncAttributeMaxDynamicSharedMemorySize,
                             (int)smem);
    }

    gmm_fused_kernel<<<sms, TPB, smem>>>(x, t, train, out, B, N, C, PL);
}

// round 12
// speedup vs baseline: 1.1828x; 1.0728x over previous
#include <cuda_runtime.h>

// GMM score, d=1, fused persistent kernel, hybrid MUFU/FMA exp, dual-query ILP.
//   sigma2(t) = (exp(2 t ln25) - 1) / (2 ln25)
//   e_ij = 2^( (k*tr + c1)*tr + c0 ),  k = -1/(2 ln2 sigma2)
//   out[j] = (num/den - x[j]) / sigma2[j]   (den==0 guard as reference)
//
// R10: each warp runs a DOUBLE unit: two query-warps (qw, qw+qhalf) against
// the same train chunk -> two independent exp chains per warp (MUFU occupancy)
// and one LDS stream for both. C chosen so double-units divide warps exactly
// (C=19 @152 SMs, 2 du/warp). phi = 1/8 poly (R6-proven). TPB=512.
// Grid barrier (monotonic epoch, grid == SM count, 1 CTA/SM resident).
// Phase B: 4 threads/query, shuffle-combined.

#define TPB       512
#define WPB       (TPB / 32)
#define MAXB      16384
#define CMAX      128

typedef unsigned long long u64;

__device__ float2 g_part[CMAX * MAXB];
__device__ unsigned int g_arrive = 0;

#define PACK2(d, lo, hi) \
    asm("mov.b64 %0, {%1, %2};" : "=l"(d) : "f"(lo), "f"(hi))
#define UNPACK2(lo, hi, s) \
    asm("mov.b64 {%0, %1}, %2;" : "=f"(lo), "=f"(hi) : "l"(s))
#define FMA2(d, a, b, c) \
    asm("fma.rn.f32x2 %0, %1, %2, %3;" : "=l"(d) : "l"(a), "l"(b), "l"(c))
#define ADD2(d, a, b) \
    asm("add.rn.f32x2 %0, %1, %2;" : "=l"(d) : "l"(a), "l"(b))
#define MUL2(d, a, b) \
    asm("mul.rn.f32x2 %0, %1, %2;" : "=l"(d) : "l"(a), "l"(b))
#define EX2(d, a) \
    asm("ex2.approx.ftz.f32 %0, %1;" : "=f"(d) : "f"(a))

struct PolyC {
    u64 MG2, MG2N, NEG1, PC4, PC3, PC2, PC1, PC0;
};

struct QState {          // per-query packed constants + accumulators
    u64 KK, C1c, C0c, num2, den2;
};

__device__ __forceinline__ float sigma2_of(float tv) {
    const float LOG_S = 3.2188758248682006f;   // ln 25
    return (expf(2.0f * tv * LOG_S) - 1.0f) / (2.0f * LOG_S);
}

// MUFU path: 4 packed FMA ops + 2 MUFU ex2 per pair
__device__ __forceinline__ void pair_mufu(u64 P, QState& s)
{
    u64 t1, a2, E;
    FMA2(t1, s.KK, P, s.C1c);
    FMA2(a2, t1, P, s.C0c);
    float al, ah, e0, e1;
    UNPACK2(al, ah, a2);
    EX2(e0, al);
    EX2(e1, ah);
    PACK2(E, e0, e1);
    FMA2(s.num2, E, P, s.num2);
    ADD2(s.den2, s.den2, E);
}

// FMA-pipe path: 12 packed fma-pipe ops + 2 IMAD (+2 FMNMX on ALU) per pair
__device__ __forceinline__ void pair_poly(u64 P, QState& s, const PolyC& pc)
{
    u64 t1, a2;
    FMA2(t1, s.KK, P, s.C1c);
    FMA2(a2, t1, P, s.C0c);
    float a0, a1;
    UNPACK2(a0, a1, a2);
    a0 = fmaxf(a0, -126.0f);                  // FMNMX (alu pipe)
    a1 = fmaxf(a1, -126.0f);
    u64 ac; PACK2(ac, a0, a1);
    u64 r2; ADD2(r2, ac, pc.MG2);             // r = a + MAGIC (round to int)
    u64 n2; ADD2(n2, r2, pc.MG2N);            // n = r - MAGIC (exact)
    u64 f2; FMA2(f2, n2, pc.NEG1, ac);        // f = a - n, f in [-0.5, 0.5]
    float r0, r1;
    UNPACK2(r0, r1, r2);
    unsigned s0 = __float_as_uint(r0) * 0x800000u + 0x3F800000u;  // 2^n bits
    unsigned s1 = __float_as_uint(r1) * 0x800000u + 0x3F800000u;
    u64 pp;
    FMA2(pp, pc.PC4, f2, pc.PC3);             // deg-4 Horner for 2^f
    FMA2(pp, pp, f2, pc.PC2);
    FMA2(pp, pp, f2, pc.PC1);
    FMA2(pp, pp, f2, pc.PC0);
    u64 S; PACK2(S, __uint_as_float(s0), __uint_as_float(s1));
    u64 E; MUL2(E, pp, S);
    FMA2(s.num2, E, P, s.num2);
    ADD2(s.den2, s.den2, E);
}

__device__ __forceinline__ void init_q(QState& s, const float* x, const float* t,
                                       int q, int B, float& sigma2_out, bool& act)
{
    act = (q < B);
    float xv = 0.0f, tv = 0.5f;
    if (act) { xv = x[q]; tv = t[q]; }
    const float INV_LN2 = 1.4426950408889634f;
    float sigma2 = sigma2_of(tv);
    sigma2_out = sigma2;
    float k  = -0.5f * INV_LN2 / sigma2;
    float c1 = -2.0f * k * xv;
    float c0 = k * xv * xv;
    PACK2(s.KK, k, k);
    PACK2(s.C1c, c1, c1);
    PACK2(s.C0c, c0, c0);
    s.num2 = 0ULL;
    s.den2 = 0ULL;
}

__global__ __launch_bounds__(TPB, 1)
void gmm_fused_kernel(const float* __restrict__ x,
                      const float* __restrict__ t,
                      const float* __restrict__ train,
                      float* __restrict__ out,
                      int B, int N, int C, int PL /* pairs/chunk, even */,
                      int qhalf)
{
    extern __shared__ u64 sp[];    // C*PL packed train pairs

    // Stage train pre-packed; pad -6e17: finite exponent chain, e==0 (mufu)
    // or ~1.2e-38 (poly, clamped) -> negligible.
    const int tot = C * PL;
    for (int i = threadIdx.x; i < tot; i += TPB) {
        int e0 = 2 * i, e1 = 2 * i + 1;
        float a = (e0 < N) ? train[e0] : -6e17f;
        float b = (e1 < N) ? train[e1] : -6e17f;
        u64 pk;
        PACK2(pk, a, b);
        sp[i] = pk;
    }
    __syncthreads();

    const int lane   = threadIdx.x & 31;
    const int wid    = threadIdx.x >> 5;
    const int wgid   = blockIdx.x * WPB + wid;
    const int nwarps = gridDim.x * WPB;

    const int du_total = qhalf * C;            // double-units

    const float MAGIC = 12582912.0f;           // 1.5 * 2^23
    PolyC pc;
    PACK2(pc.MG2,  MAGIC,  MAGIC);
    PACK2(pc.MG2N, -MAGIC, -MAGIC);
    PACK2(pc.NEG1, -1.0f, -1.0f);
    {
        const float c4 = 0.0096181291f, c3 = 0.0555041087f,
                    c2 = 0.2402265070f, c1p = 0.6931471806f, c0p = 1.0f;
        PACK2(pc.PC4, c4, c4); PACK2(pc.PC3, c3, c3); PACK2(pc.PC2, c2, c2);
        PACK2(pc.PC1, c1p, c1p); PACK2(pc.PC0, c0p, c0p);
    }

    // ---- phase A: dual-query units ----
    for (int du = wgid; du < du_total; du += nwarps) {
        const int qw1 = du / C;
        const int c   = du - qw1 * C;
        const int q1  = qw1 * 32 + lane;
        const int q2  = (qw1 + qhalf) * 32 + lane;

        QState s1, s2;
        float sg1, sg2;
        bool act1, act2;
        init_q(s1, x, t, q1, B, sg1, act1);
        init_q(s2, x, t, q2, B, sg2, act2);

        const ulonglong2* __restrict__ p =
            reinterpret_cast<const ulonglong2*>(sp + c * PL);
        const int iters  = PL >> 1;            // vec4 loads (2 pairs each)
        const int blocks = iters >> 2;         // 8 pairs per block

        int i = 0;
        for (int b = 0; b < blocks; ++b, i += 4) {
            ulonglong2 v0 = p[i + 0];
            ulonglong2 v1 = p[i + 1];
            pair_mufu(v0.x, s1); pair_mufu(v0.x, s2);         // 0
            pair_mufu(v0.y, s1); pair_mufu(v0.y, s2);         // 1
            pair_mufu(v1.x, s1); pair_mufu(v1.x, s2);         // 2
            pair_poly(v1.y, s1, pc); pair_poly(v1.y, s2, pc); // 3  (1/8)
            ulonglong2 v2 = p[i + 2];
            ulonglong2 v3 = p[i + 3];
            pair_mufu(v2.x, s1); pair_mufu(v2.x, s2);         // 4
            pair_mufu(v2.y, s1); pair_mufu(v2.y, s2);         // 5
            pair_mufu(v3.x, s1); pair_mufu(v3.x, s2);         // 6
            pair_mufu(v3.y, s1); pair_mufu(v3.y, s2);         // 7
        }
        for (; i < iters; ++i) {               // tail pairs (mufu)
            ulonglong2 v = p[i];
            pair_mufu(v.x, s1); pair_mufu(v.x, s2);
            pair_mufu(v.y, s1); pair_mufu(v.y, s2);
        }

        float nlo, nhi, dlo, dhi;
        if (act1) {
            UNPACK2(nlo, nhi, s1.num2);
            UNPACK2(dlo, dhi, s1.den2);
            g_part[c * MAXB + q1] = make_float2(nlo + nhi, dlo + dhi);
        }
        if (act2) {
            UNPACK2(nlo, nhi, s2.num2);
            UNPACK2(dlo, dhi, s2.den2);
            g_part[c * MAXB + q2] = make_float2(nlo + nhi, dlo + dhi);
        }
    }

    // ---- grid barrier (monotonic epoch; grid == SM count, all resident) ----
    __syncthreads();
    if (threadIdx.x == 0) {
        __threadfence();
        unsigned old = atomicAdd(&g_arrive, 1u);
        unsigned target = (old / gridDim.x + 1u) * gridDim.x;
        while (*((volatile unsigned int*)&g_arrive) < target) { }
    }
    __syncthreads();
    __threadfence();

    // ---- phase B: S threads per query, shuffle combine ----
    const int T  = gridDim.x * TPB;
    const int tg = blockIdx.x * TPB + threadIdx.x;
    int ls;                                       // log2(S)
    if      (T >= 4 * B) ls = 2;
    else if (T >= 2 * B) ls = 1;
    else                 ls = 0;
    const int S   = 1 << ls;
    const int gq  = tg >> ls;
    const int sub = tg & (S - 1);

    if (gq < B) {
        float num = 0.0f, den = 0.0f;
        for (int c = sub; c < C; c += S) {
            float2 pd = g_part[c * MAXB + gq];
            num += pd.x;
            den += pd.y;
        }
        for (int off = S >> 1; off > 0; off >>= 1) {
            num += __shfl_down_sync(0xffffffffu, num, off);
            den += __shfl_down_sync(0xffffffffu, den, off);
        }
        if (sub == 0) {
            float xv = x[gq];
            float sigma2 = sigma2_of(t[gq]);
            float evals = (den == 0.0f) ? 0.0f : (num / den);
            out[gq] = (evals - xv) / sigma2;
        }
    }
}

static int gcd_i(int a, int b) { while (b) { int r = a % b; a = b; b = r; } return a; }

extern "C" void kernel_launch(void* const* d_in, const int* in_sizes, int n_in,
                              void* d_out, int out_size)
{
    const float* x     = (const float*)d_in[0];
    const float* t     = (const float*)d_in[1];
    const float* train = (const float*)d_in[2];
    float* out = (float*)d_out;

    int B = in_sizes[0];   // 16384
    int N = in_sizes[2];   // 16384

    static int sms = 0;
    static int C = 0, PL = 0, qhalf = 0;
    static size_t smem = 0;
    if (!sms) {
        cudaDeviceGetAttribute(&sms, cudaDevAttrMultiProcessorCount, 0);
        if (sms <= 0) sms = 148;

        int warps  = sms * WPB;
        int qwarps = (B + 31) / 32;
        qhalf = (qwarps + 1) / 2;                  // dual-query: qw and qw+qhalf
        C = warps / gcd_i(qhalf, warps);           // exact balance on double-units
        if (C > CMAX) C = CMAX;                    // fallback (imperfect balance)
        if (C < 4)  C *= (4 + C - 1) / C;          // enough chunks for phase B
        int npairs = (N + 1) / 2;
        PL = (npairs + C - 1) / C;
        PL = (PL + 1) & ~1;                        // even (vec4 LDS)
        smem = (size_t)C * PL * sizeof(u64);
        cudaFuncSetAttribute(gmm_fused_kernel,
                             cudaFuncAttributeMaxDynamicSharedMemorySize,
                             (int)smem);
    }

    gmm_fused_kernel<<<sms, TPB, smem>>>(x, t, train, out, B, N, C, PL, qhalf);
}

// round 13
// speedup vs baseline: 1.2479x; 1.0550x over previous
#include <cuda_runtime.h>

// GMM score, d=1, fused persistent kernel, hybrid MUFU/FMA exp, QUAD-query ILP.
//   sigma2(t) = (exp(2 t ln25) - 1) / (2 ln25)
//   e_ij = 2^( (k*tr + c1)*tr + c0 ),  k = -1/(2 ln2 sigma2)
//   out[j] = (num/den - x[j]) / sigma2[j]   (den==0 guard as reference)
//
// R11: each warp runs a QUAD unit: four query-warps (qw + m*qquart) against
// one train chunk -> four independent exp chains (MUFU occupancy 87% -> ~95%)
// and one LDS stream for all four. C chosen so quad-units divide warps exactly
// (C=19 @152 SMs -> exactly 1 unit/warp). phi = 1/8 poly (proven optimum).
// Grid barrier (monotonic epoch, grid == SM count, 1 CTA/SM resident).
// Phase B: 4 threads/query, shuffle-combined.

#define TPB       512
#define WPB       (TPB / 32)
#define MAXB      16384
#define CMAX      128

typedef unsigned long long u64;

__device__ float2 g_part[CMAX * MAXB];
__device__ unsigned int g_arrive = 0;

#define PACK2(d, lo, hi) \
    asm("mov.b64 %0, {%1, %2};" : "=l"(d) : "f"(lo), "f"(hi))
#define UNPACK2(lo, hi, s) \
    asm("mov.b64 {%0, %1}, %2;" : "=f"(lo), "=f"(hi) : "l"(s))
#define FMA2(d, a, b, c) \
    asm("fma.rn.f32x2 %0, %1, %2, %3;" : "=l"(d) : "l"(a), "l"(b), "l"(c))
#define ADD2(d, a, b) \
    asm("add.rn.f32x2 %0, %1, %2;" : "=l"(d) : "l"(a), "l"(b))
#define MUL2(d, a, b) \
    asm("mul.rn.f32x2 %0, %1, %2;" : "=l"(d) : "l"(a), "l"(b))
#define EX2(d, a) \
    asm("ex2.approx.ftz.f32 %0, %1;" : "=f"(d) : "f"(a))

struct PolyC {
    u64 MG2, MG2N, NEG1, PC4, PC3, PC2, PC1, PC0;
};

struct QState {          // per-query packed constants + accumulators
    u64 KK, C1c, C0c, num2, den2;
};

__device__ __forceinline__ float sigma2_of(float tv) {
    const float LOG_S = 3.2188758248682006f;   // ln 25
    return (expf(2.0f * tv * LOG_S) - 1.0f) / (2.0f * LOG_S);
}

// MUFU path: 4 packed FMA ops + 2 MUFU ex2 per pair
__device__ __forceinline__ void pair_mufu(u64 P, QState& s)
{
    u64 t1, a2, E;
    FMA2(t1, s.KK, P, s.C1c);
    FMA2(a2, t1, P, s.C0c);
    float al, ah, e0, e1;
    UNPACK2(al, ah, a2);
    EX2(e0, al);
    EX2(e1, ah);
    PACK2(E, e0, e1);
    FMA2(s.num2, E, P, s.num2);
    ADD2(s.den2, s.den2, E);
}

// FMA-pipe path: 12 packed fma-pipe ops + 2 IMAD (+2 FMNMX on ALU) per pair
__device__ __forceinline__ void pair_poly(u64 P, QState& s, const PolyC& pc)
{
    u64 t1, a2;
    FMA2(t1, s.KK, P, s.C1c);
    FMA2(a2, t1, P, s.C0c);
    float a0, a1;
    UNPACK2(a0, a1, a2);
    a0 = fmaxf(a0, -126.0f);                  // FMNMX (alu pipe)
    a1 = fmaxf(a1, -126.0f);
    u64 ac; PACK2(ac, a0, a1);
    u64 r2; ADD2(r2, ac, pc.MG2);             // r = a + MAGIC (round to int)
    u64 n2; ADD2(n2, r2, pc.MG2N);            // n = r - MAGIC (exact)
    u64 f2; FMA2(f2, n2, pc.NEG1, ac);        // f = a - n, f in [-0.5, 0.5]
    float r0, r1;
    UNPACK2(r0, r1, r2);
    unsigned s0 = __float_as_uint(r0) * 0x800000u + 0x3F800000u;  // 2^n bits
    unsigned s1 = __float_as_uint(r1) * 0x800000u + 0x3F800000u;
    u64 pp;
    FMA2(pp, pc.PC4, f2, pc.PC3);             // deg-4 Horner for 2^f
    FMA2(pp, pp, f2, pc.PC2);
    FMA2(pp, pp, f2, pc.PC1);
    FMA2(pp, pp, f2, pc.PC0);
    u64 S; PACK2(S, __uint_as_float(s0), __uint_as_float(s1));
    u64 E; MUL2(E, pp, S);
    FMA2(s.num2, E, P, s.num2);
    ADD2(s.den2, s.den2, E);
}

__device__ __forceinline__ void init_q(QState& s, const float* x, const float* t,
                                       int q, int B, bool& act)
{
    act = (q < B);
    float xv = 0.0f, tv = 0.5f;
    if (act) { xv = x[q]; tv = t[q]; }
    const float INV_LN2 = 1.4426950408889634f;
    float sigma2 = sigma2_of(tv);
    float k  = -0.5f * INV_LN2 / sigma2;
    float c1 = -2.0f * k * xv;
    float c0 = k * xv * xv;
    PACK2(s.KK, k, k);
    PACK2(s.C1c, c1, c1);
    PACK2(s.C0c, c0, c0);
    s.num2 = 0ULL;
    s.den2 = 0ULL;
}

__device__ __forceinline__ void store_q(const QState& s, int c, int q, bool act)
{
    if (act) {
        float nlo, nhi, dlo, dhi;
        UNPACK2(nlo, nhi, s.num2);
        UNPACK2(dlo, dhi, s.den2);
        g_part[c * MAXB + q] = make_float2(nlo + nhi, dlo + dhi);
    }
}

__global__ __launch_bounds__(TPB, 1)
void gmm_fused_kernel(const float* __restrict__ x,
                      const float* __restrict__ t,
                      const float* __restrict__ train,
                      float* __restrict__ out,
                      int B, int N, int C, int PL /* pairs/chunk, even */,
                      int qquart)
{
    extern __shared__ u64 sp[];    // C*PL packed train pairs

    // Stage train pre-packed; pad -6e17: finite exponent chain, e==0 (mufu)
    // or ~1.2e-38 (poly, clamped) -> negligible.
    const int tot = C * PL;
    for (int i = threadIdx.x; i < tot; i += TPB) {
        int e0 = 2 * i, e1 = 2 * i + 1;
        float a = (e0 < N) ? train[e0] : -6e17f;
        float b = (e1 < N) ? train[e1] : -6e17f;
        u64 pk;
        PACK2(pk, a, b);
        sp[i] = pk;
    }
    __syncthreads();

    const int lane   = threadIdx.x & 31;
    const int wid    = threadIdx.x >> 5;
    const int wgid   = blockIdx.x * WPB + wid;
    const int nwarps = gridDim.x * WPB;

    const int qu_total = qquart * C;           // quad-units

    const float MAGIC = 12582912.0f;           // 1.5 * 2^23
    PolyC pc;
    PACK2(pc.MG2,  MAGIC,  MAGIC);
    PACK2(pc.MG2N, -MAGIC, -MAGIC);
    PACK2(pc.NEG1, -1.0f, -1.0f);
    {
        const float c4 = 0.0096181291f, c3 = 0.0555041087f,
                    c2 = 0.2402265070f, c1p = 0.6931471806f, c0p = 1.0f;
        PACK2(pc.PC4, c4, c4); PACK2(pc.PC3, c3, c3); PACK2(pc.PC2, c2, c2);
        PACK2(pc.PC1, c1p, c1p); PACK2(pc.PC0, c0p, c0p);
    }

    // ---- phase A: quad-query units (1 unit/warp at 152 SMs) ----
    for (int qu = wgid; qu < qu_total; qu += nwarps) {
        const int qw1 = qu / C;
        const int c   = qu - qw1 * C;
        const int q1  = qw1 * 32 + lane;
        const int q2  = (qw1 + qquart)     * 32 + lane;
        const int q3  = (qw1 + 2 * qquart) * 32 + lane;
        const int q4  = (qw1 + 3 * qquart) * 32 + lane;

        QState s1, s2, s3, s4;
        bool a1, a2, a3, a4;
        init_q(s1, x, t, q1, B, a1);
        init_q(s2, x, t, q2, B, a2);
        init_q(s3, x, t, q3, B, a3);
        init_q(s4, x, t, q4, B, a4);

        const ulonglong2* __restrict__ p =
            reinterpret_cast<const ulonglong2*>(sp + c * PL);
        const int iters  = PL >> 1;            // vec4 loads (2 pairs each)
        const int blocks = iters >> 2;         // 8 pairs per block

        int i = 0;
        for (int b = 0; b < blocks; ++b, i += 4) {
            ulonglong2 v0 = p[i + 0];
            ulonglong2 v1 = p[i + 1];
            pair_mufu(v0.x, s1); pair_mufu(v0.x, s2);
            pair_mufu(v0.x, s3); pair_mufu(v0.x, s4);
            pair_mufu(v0.y, s1); pair_mufu(v0.y, s2);
            pair_mufu(v0.y, s3); pair_mufu(v0.y, s4);
            pair_mufu(v1.x, s1); pair_mufu(v1.x, s2);
            pair_mufu(v1.x, s3); pair_mufu(v1.x, s4);
            pair_poly(v1.y, s1, pc); pair_poly(v1.y, s2, pc);   // 1/8 poly
            pair_poly(v1.y, s3, pc); pair_poly(v1.y, s4, pc);
            ulonglong2 v2 = p[i + 2];
            ulonglong2 v3 = p[i + 3];
            pair_mufu(v2.x, s1); pair_mufu(v2.x, s2);
            pair_mufu(v2.x, s3); pair_mufu(v2.x, s4);
            pair_mufu(v2.y, s1); pair_mufu(v2.y, s2);
            pair_mufu(v2.y, s3); pair_mufu(v2.y, s4);
            pair_mufu(v3.x, s1); pair_mufu(v3.x, s2);
            pair_mufu(v3.x, s3); pair_mufu(v3.x, s4);
            pair_mufu(v3.y, s1); pair_mufu(v3.y, s2);
            pair_mufu(v3.y, s3); pair_mufu(v3.y, s4);
        }
        for (; i < iters; ++i) {               // tail pairs (mufu)
            ulonglong2 v = p[i];
            pair_mufu(v.x, s1); pair_mufu(v.x, s2);
            pair_mufu(v.x, s3); pair_mufu(v.x, s4);
            pair_mufu(v.y, s1); pair_mufu(v.y, s2);
            pair_mufu(v.y, s3); pair_mufu(v.y, s4);
        }

        store_q(s1, c, q1, a1);
        store_q(s2, c, q2, a2);
        store_q(s3, c, q3, a3);
        store_q(s4, c, q4, a4);
    }

    // ---- grid barrier (monotonic epoch; grid == SM count, all resident) ----
    __syncthreads();
    if (threadIdx.x == 0) {
        __threadfence();
        unsigned old = atomicAdd(&g_arrive, 1u);
        unsigned target = (old / gridDim.x + 1u) * gridDim.x;
        while (*((volatile unsigned int*)&g_arrive) < target) { }
    }
    __syncthreads();
    __threadfence();

    // ---- phase B: S threads per query, shuffle combine ----
    const int T  = gridDim.x * TPB;
    const int tg = blockIdx.x * TPB + threadIdx.x;
    int ls;                                       // log2(S)
    if      (T >= 4 * B) ls = 2;
    else if (T >= 2 * B) ls = 1;
    else                 ls = 0;
    const int S   = 1 << ls;
    const int gq  = tg >> ls;
    const int sub = tg & (S - 1);

    if (gq < B) {
        float num = 0.0f, den = 0.0f;
        for (int c = sub; c < C; c += S) {
            float2 pd = g_part[c * MAXB + gq];
            num += pd.x;
            den += pd.y;
        }
        for (int off = S >> 1; off > 0; off >>= 1) {
            num += __shfl_down_sync(0xffffffffu, num, off);
            den += __shfl_down_sync(0xffffffffu, den, off);
        }
        if (sub == 0) {
            float xv = x[gq];
            float sigma2 = sigma2_of(t[gq]);
            float evals = (den == 0.0f) ? 0.0f : (num / den);
            out[gq] = (evals - xv) / sigma2;
        }
    }
}

static int gcd_i(int a, int b) { while (b) { int r = a % b; a = b; b = r; } return a; }

extern "C" void kernel_launch(void* const* d_in, const int* in_sizes, int n_in,
                              void* d_out, int out_size)
{
    const float* x     = (const float*)d_in[0];
    const float* t     = (const float*)d_in[1];
    const float* train = (const float*)d_in[2];
    float* out = (float*)d_out;

    int B = in_sizes[0];   // 16384
    int N = in_sizes[2];   // 16384

    static int sms = 0;
    static int C = 0, PL = 0, qquart = 0;
    static size_t smem = 0;
    if (!sms) {
        cudaDeviceGetAttribute(&sms, cudaDevAttrMultiProcessorCount, 0);
        if (sms <= 0) sms = 148;

        int warps  = sms * WPB;
        int qwarps = (B + 31) / 32;
        qquart = (qwarps + 3) / 4;                 // quad-query stride
        C = warps / gcd_i(qquart, warps);          // exact balance on quad-units
        if (C > CMAX) C = CMAX;                    // fallback (imperfect balance)
        if (C < 4)  C *= (4 + C - 1) / C;          // enough chunks for phase B
        int npairs = (N + 1) / 2;
        PL = (npairs + C - 1) / C;
        PL = (PL + 1) & ~1;                        // even (vec4 LDS)
        smem = (size_t)C * PL * sizeof(u64);
        cudaFuncSetAttribute(gmm_fused_kernel,
                             cudaFuncAttributeMaxDynamicSharedMemorySize,
                             (int)smem);
    }

    gmm_fused_kernel<<<sms, TPB, smem>>>(x, t, train, out, B, N, C, PL, qquart);
}